// round 11
// baseline (speedup 1.0000x reference)
#include <cuda_runtime.h>
#include <cuda_bf16.h>

// Dilate (zero-insertion upsample) with stride (2,2):
//   in : (16, 64, 256, 256) fp32
//   out: (16, 64, 512, 512) fp32, out[b,c,2i,2j] = in[b,c,i,j], rest 0.
//
// R5 structure (measured optimum over 10 rounds):
//   - one output row (2KB = 128 float4) per WARP; four warp-contiguous
//     512B stores; warp-uniform parity branch; MLP=4 front-batched loads;
//     streaming cache hints.
// This round: block size 256 -> 128. R7 showed block=512 collapses DRAM%
// via per-SM L1tex queue saturation (16 warps x MLP4 in lockstep); 128
// probes the remaining untested point in the direction that helped.
// Traffic: 268MB read + 1.074GB write = the exact floor.

#ifndef DIL_THREADS
#define DIL_THREADS 128
#endif

__global__ void __launch_bounds__(DIL_THREADS)
Dilate_35708358099161_kernel(const float2* __restrict__ in2,
                             float4* __restrict__ out4)
{
    unsigned int tid  = blockIdx.x * DIL_THREADS + threadIdx.x;
    unsigned int row  = tid >> 5;        // global output row, one per warp
    unsigned int lane = tid & 31u;

    unsigned int h = row & 511u;         // out row within image
    unsigned int v = (row << 7) + lane;  // first float4 index for this lane

    const float4 z = make_float4(0.f, 0.f, 0.f, 0.f);

    if (h & 1u) {
        __stcs(&out4[v],       z);
        __stcs(&out4[v + 32],  z);
        __stcs(&out4[v + 64],  z);
        __stcs(&out4[v + 96],  z);
    } else {
        unsigned int bc   = row >> 9;    // image index, 0..1023
        unsigned int hin  = h >> 1;      // input row, 0..255
        unsigned int base = (bc << 15) + (hin << 7) + lane;  // float2 units

        // four independent 256B-coalesced loads (full 1KB input row per warp)
        float2 a = __ldcs(&in2[base]);
        float2 b = __ldcs(&in2[base + 32]);
        float2 c = __ldcs(&in2[base + 64]);
        float2 d = __ldcs(&in2[base + 96]);

        __stcs(&out4[v],      make_float4(a.x, 0.f, a.y, 0.f));
        __stcs(&out4[v + 32], make_float4(b.x, 0.f, b.y, 0.f));
        __stcs(&out4[v + 64], make_float4(c.x, 0.f, c.y, 0.f));
        __stcs(&out4[v + 96], make_float4(d.x, 0.f, d.y, 0.f));
    }
}

extern "C" void kernel_launch(void* const* d_in, const int* in_sizes, int n_in,
                              void* d_out, int out_size)
{
    const float2* in2 = (const float2*)d_in[0];
    float4* out4 = (float4*)d_out;

    // out rows = out_size / 512 = 524,288; one warp per row
    const unsigned int nthreads = (unsigned int)(out_size / 16);
    const unsigned int blocks = nthreads / DIL_THREADS;  // exact: 131,072

    Dilate_35708358099161_kernel<<<blocks, DIL_THREADS>>>(in2, out4);
}

// round 12
// speedup vs baseline: 1.0021x; 1.0021x over previous
#include <cuda_runtime.h>
#include <cuda_bf16.h>

// Dilate (zero-insertion upsample) with stride (2,2):
//   in : (16, 64, 256, 256) fp32
//   out: (16, 64, 512, 512) fp32, out[b,c,2i,2j] = in[b,c,i,j], rest 0.
//
// FINAL — measured optimum across 11 rounds (3 independent ncu runs of this
// exact structure: 192.0 / 195.5 / 191.7 us, DRAM 84+-1%, ~6.65 TB/s):
//   - one output row (2KB = 128 float4) per WARP; lane handles float4
//     offsets lane + {0,32,64,96} -> four warp-contiguous 512B stores
//     (strided stores cost 6%: R2)
//   - warp-uniform parity branch kept (branch-free pair-per-warp slower: R6)
//   - four front-batched 256B-coalesced loads, MLP=4 (monotone gain 1->2->4:
//     R1/R3/R5)
//   - 256 threads/block (128: 82.5% DRAM, 256: 84.4%, 512: 75.8% via per-SM
//     L1tex queue saturation: R7/R11)
//   - streaming cache hints; 256-bit stores tested with no effect (R9)
// Traffic: 268MB read + 1.074GB write = the exact floor. Residual gap to
// spec BW is DRAM bus-turnaround/protocol overhead on a 4:1 W:R stream.

#ifndef DIL_THREADS
#define DIL_THREADS 256
#endif

__global__ void __launch_bounds__(DIL_THREADS)
Dilate_35708358099161_kernel(const float2* __restrict__ in2,
                             float4* __restrict__ out4)
{
    unsigned int tid  = blockIdx.x * DIL_THREADS + threadIdx.x;
    unsigned int row  = tid >> 5;        // global output row, one per warp
    unsigned int lane = tid & 31u;

    unsigned int h = row & 511u;         // out row within image
    unsigned int v = (row << 7) + lane;  // first float4 index for this lane

    const float4 z = make_float4(0.f, 0.f, 0.f, 0.f);

    if (h & 1u) {
        __stcs(&out4[v],       z);
        __stcs(&out4[v + 32],  z);
        __stcs(&out4[v + 64],  z);
        __stcs(&out4[v + 96],  z);
    } else {
        unsigned int bc   = row >> 9;    // image index, 0..1023
        unsigned int hin  = h >> 1;      // input row, 0..255
        unsigned int base = (bc << 15) + (hin << 7) + lane;  // float2 units

        // four independent 256B-coalesced loads (full 1KB input row per warp)
        float2 a = __ldcs(&in2[base]);
        float2 b = __ldcs(&in2[base + 32]);
        float2 c = __ldcs(&in2[base + 64]);
        float2 d = __ldcs(&in2[base + 96]);

        __stcs(&out4[v],      make_float4(a.x, 0.f, a.y, 0.f));
        __stcs(&out4[v + 32], make_float4(b.x, 0.f, b.y, 0.f));
        __stcs(&out4[v + 64], make_float4(c.x, 0.f, c.y, 0.f));
        __stcs(&out4[v + 96], make_float4(d.x, 0.f, d.y, 0.f));
    }
}

extern "C" void kernel_launch(void* const* d_in, const int* in_sizes, int n_in,
                              void* d_out, int out_size)
{
    const float2* in2 = (const float2*)d_in[0];
    float4* out4 = (float4*)d_out;

    // out rows = out_size / 512 = 524,288; one warp per row
    const unsigned int nthreads = (unsigned int)(out_size / 16);
    const unsigned int blocks = nthreads / DIL_THREADS;  // exact: 65,536

    Dilate_35708358099161_kernel<<<blocks, DIL_THREADS>>>(in2, out4);
}

// round 13
// speedup vs baseline: 1.0172x; 1.0151x over previous
#include <cuda_runtime.h>
#include <cuda_bf16.h>

// Dilate (zero-insertion upsample) with stride (2,2):
//   in : (16, 64, 256, 256) fp32
//   out: (16, 64, 512, 512) fp32, out[b,c,2i,2j] = in[b,c,i,j], rest 0.
//
// Measured-optimal structure (4 ncu runs: 193.4 +- 1.8 us, DRAM 83.7 +- 0.8%):
//   one 2KB output row per warp, four warp-contiguous 512B stores,
//   warp-uniform parity branch, MLP=4 front-batched loads, 256 thr/block.
// This round's isolated A/B: DROP the .cs evict-first hint on stores
// (keep __ldcs on read-once loads). Hypothesis: evict-first may force L2 to
// emit eager/smaller DRAM write bursts; default policy lets LTS coalesce
// writebacks into longer trains on this 4:1 W:R stream.
// Traffic: 268MB read + 1.074GB write = the exact floor.

#ifndef DIL_THREADS
#define DIL_THREADS 256
#endif

__global__ void __launch_bounds__(DIL_THREADS)
Dilate_35708358099161_kernel(const float2* __restrict__ in2,
                             float4* __restrict__ out4)
{
    unsigned int tid  = blockIdx.x * DIL_THREADS + threadIdx.x;
    unsigned int row  = tid >> 5;        // global output row, one per warp
    unsigned int lane = tid & 31u;

    unsigned int h = row & 511u;         // out row within image
    unsigned int v = (row << 7) + lane;  // first float4 index for this lane

    const float4 z = make_float4(0.f, 0.f, 0.f, 0.f);

    if (h & 1u) {
        out4[v]      = z;
        out4[v + 32] = z;
        out4[v + 64] = z;
        out4[v + 96] = z;
    } else {
        unsigned int bc   = row >> 9;    // image index, 0..1023
        unsigned int hin  = h >> 1;      // input row, 0..255
        unsigned int base = (bc << 15) + (hin << 7) + lane;  // float2 units

        // four independent 256B-coalesced loads (full 1KB input row per warp)
        float2 a = __ldcs(&in2[base]);
        float2 b = __ldcs(&in2[base + 32]);
        float2 c = __ldcs(&in2[base + 64]);
        float2 d = __ldcs(&in2[base + 96]);

        out4[v]      = make_float4(a.x, 0.f, a.y, 0.f);
        out4[v + 32] = make_float4(b.x, 0.f, b.y, 0.f);
        out4[v + 64] = make_float4(c.x, 0.f, c.y, 0.f);
        out4[v + 96] = make_float4(d.x, 0.f, d.y, 0.f);
    }
}

extern "C" void kernel_launch(void* const* d_in, const int* in_sizes, int n_in,
                              void* d_out, int out_size)
{
    const float2* in2 = (const float2*)d_in[0];
    float4* out4 = (float4*)d_out;

    // out rows = out_size / 512 = 524,288; one warp per row
    const unsigned int nthreads = (unsigned int)(out_size / 16);
    const unsigned int blocks = nthreads / DIL_THREADS;  // exact: 65,536

    Dilate_35708358099161_kernel<<<blocks, DIL_THREADS>>>(in2, out4);
}